// round 6
// baseline (speedup 1.0000x reference)
#include <cuda_runtime.h>
#include <cuda_fp16.h>
#include <cstdint>

// ---------------------------------------------------------------------------
// Problem constants
//   x:      [8, 4096, 512]  fp32
//   w_qkv:  [512, 1536]     fp32
//   out:    [2, 8, 4, 4096, 64] fp32
// g_qkv16 scratch: [32768, 1536] fp16 (q: 0..511, k: 512..1023, v: 1024..1535)
// ---------------------------------------------------------------------------
#define B_      8
#define NTOK    4096
#define DIM     512
#define QKVC    1536
#define NT_     16
#define S_      256
#define H2_     4
#define DH      64
#define M_TOT   (B_ * NTOK)          // 32768

__device__ __half g_qkv16[(size_t)M_TOT * QKVC];    // 100 MB
__device__ __half g_A[(size_t)M_TOT * DIM];         // 32 MB  [M, 512] fp16
__device__ __half g_B[(size_t)QKVC * DIM];          // 1.5 MB [N, 512] fp16 (K-major)

// ===========================================================================
// helpers
// ===========================================================================
__device__ __forceinline__ uint32_t smem_u32(const void* p) {
    uint32_t a;
    asm("{ .reg .u64 t; cvta.to.shared.u64 t, %1; cvt.u32.u64 %0, t; }"
        : "=r"(a) : "l"(p));
    return a;
}

#define SMEM_SWIZZLE_128B(byte_offset) \
    ((byte_offset) ^ (((byte_offset) >> 3) & 0x70))

__device__ __forceinline__ void ldsm_x4(uint32_t* r, uint32_t addr) {
    asm volatile("ldmatrix.sync.aligned.m8n8.x4.shared.b16 {%0,%1,%2,%3}, [%4];"
        : "=r"(r[0]), "=r"(r[1]), "=r"(r[2]), "=r"(r[3]) : "r"(addr));
}

__device__ __forceinline__ void ldsm_x4_t(uint32_t* r, uint32_t addr) {
    asm volatile("ldmatrix.sync.aligned.m8n8.x4.trans.shared.b16 {%0,%1,%2,%3}, [%4];"
        : "=r"(r[0]), "=r"(r[1]), "=r"(r[2]), "=r"(r[3]) : "r"(addr));
}

__device__ __forceinline__ void mma16816(float* d, const uint32_t* a,
                                         uint32_t b0, uint32_t b1) {
    asm volatile(
        "mma.sync.aligned.m16n8k16.row.col.f32.f16.f16.f32 "
        "{%0,%1,%2,%3}, {%4,%5,%6,%7}, {%8,%9}, {%0,%1,%2,%3};"
        : "+f"(d[0]), "+f"(d[1]), "+f"(d[2]), "+f"(d[3])
        : "r"(a[0]), "r"(a[1]), "r"(a[2]), "r"(a[3]), "r"(b0), "r"(b1));
}

__device__ __forceinline__ uint32_t pack_h2(float a, float b) {
    __half2 h = __floats2half2_rn(a, b);
    return *(uint32_t*)&h;
}

__device__ __forceinline__ void h8_to_f8(uint4 u, float* f) {
    const __half2* hp = (const __half2*)&u;
    #pragma unroll
    for (int m = 0; m < 4; m++) {
        float2 t = __half22float2(hp[m]);
        f[2 * m] = t.x; f[2 * m + 1] = t.y;
    }
}

// ===========================================================================
// Fused conversion: fp32 -> fp16 for A (x) and B (w, transposed)
// blocks [0, 16384): A ; blocks [16384, 19456): B
// ===========================================================================
#define NA_BLK (M_TOT * 128 / 256)      // 16384
#define NB_BLK (QKVC * 512 / 256 / 256) // 12 -> actually computed below

__global__ void __launch_bounds__(256)
conv_ab(const float* __restrict__ x, const float* __restrict__ w)
{
    const int bidx = blockIdx.x;
    if (bidx < NA_BLK) {
        size_t idx = (size_t)bidx * 256 + threadIdx.x;   // 0 .. 32768*128-1
        size_t m = idx >> 7;
        int k4 = (int)(idx & 127);
        float4 v = *(const float4*)(x + m * DIM + (size_t)k4 * 4);
        __align__(8) __half h[4];
        h[0] = __float2half_rn(v.x);
        h[1] = __float2half_rn(v.y);
        h[2] = __float2half_rn(v.z);
        h[3] = __float2half_rn(v.w);
        *(uint2*)&g_A[m * DIM + (size_t)k4 * 4] = *(uint2*)h;
    } else {
        int idx = (bidx - NA_BLK) * 256 + threadIdx.x;   // 0..786431
        int n = idx >> 9;
        int k = idx & 511;
        g_B[(size_t)n * DIM + k] = __float2half_rn(w[(size_t)k * QKVC + n]);
    }
}

// ===========================================================================
// mma.sync fp16 GEMM: g_qkv16[M,1536] = A[M,512] @ B[N,512]^T  (fp32 accum)
// 256x128 block tile, BK=64 (8 chunks), 3-stage cp.async pipeline,
// 8 warps with 64x64 warp tiles.
// ===========================================================================
#define STAGES 3
#define CHUNKS 8
#define KC 64
#define STAGE_BYTES 49152   // A tile 32KB + B tile 16KB

__global__ void __launch_bounds__(256, 1)
qkv_gemm_mma()
{
    extern __shared__ char dsm_raw[];
    const uint32_t tile_base = smem_u32(dsm_raw);

    const int tid  = threadIdx.x;
    const int wid  = tid >> 5;
    const int lane = tid & 31;
    const int wm = wid & 3;          // 0..3 -> 64-row strip
    const int wn = wid >> 2;         // 0..1 -> 64-col strip
    const int bx = blockIdx.x;       // N tile 0..11
    const int by = blockIdx.y;       // M tile 0..127

    const size_t m0 = (size_t)by * 256;
    const size_t n0 = (size_t)bx * 128;

    // B-load indexing: 2 threads per row
    const int rowB  = tid >> 1;             // 0..127
    const int colB  = (tid & 1) * 64;       // byte col 0 or 64

    auto load_chunk = [&](int c, int s) {
        const int kk = c * KC;
        const uint32_t abase = tile_base + s * STAGE_BYTES;
        const uint32_t bbase = abase + 32768;
        // A: each thread loads its own row (256 rows), 8 x 16B
        const __half* srcA = g_A + (m0 + tid) * DIM + kk;
        #pragma unroll
        for (int i = 0; i < 8; i++) {
            const uint32_t off = SMEM_SWIZZLE_128B((uint32_t)(tid * 128 + i * 16));
            asm volatile("cp.async.cg.shared.global [%0], [%1], 16;"
                         :: "r"(abase + off), "l"(srcA + i * 8) : "memory");
        }
        // B: 128 rows, 2 threads/row, 4 x 16B each
        const __half* srcB = g_B + (n0 + rowB) * DIM + kk + colB / 2;
        #pragma unroll
        for (int i = 0; i < 4; i++) {
            const uint32_t off = SMEM_SWIZZLE_128B((uint32_t)(rowB * 128 + colB + i * 16));
            asm volatile("cp.async.cg.shared.global [%0], [%1], 16;"
                         :: "r"(bbase + off), "l"(srcB + i * 8) : "memory");
        }
    };

    float acc[4][8][4];
    #pragma unroll
    for (int mf = 0; mf < 4; mf++)
        #pragma unroll
        for (int nf = 0; nf < 8; nf++)
            #pragma unroll
            for (int i = 0; i < 4; i++) acc[mf][nf][i] = 0.f;

    load_chunk(0, 0);
    asm volatile("cp.async.commit_group;" ::: "memory");
    load_chunk(1, 1);
    asm volatile("cp.async.commit_group;" ::: "memory");

    const int lrow  = lane & 15;
    const int lhalf = (lane >> 4) * 16;

    #pragma unroll 1
    for (int c = 0; c < CHUNKS; c++) {
        asm volatile("cp.async.wait_group 1;" ::: "memory");
        __syncthreads();

        if (c + 2 < CHUNKS) load_chunk(c + 2, (c + 2) % STAGES);
        asm volatile("cp.async.commit_group;" ::: "memory");

        const uint32_t abase = tile_base + (c % STAGES) * STAGE_BYTES;
        const uint32_t bbase = abase + 32768;

        #pragma unroll
        for (int k16 = 0; k16 < 4; k16++) {
            const uint32_t colb = (uint32_t)(k16 * 32 + lhalf);
            uint32_t afr[4][4];
            #pragma unroll
            for (int mf = 0; mf < 4; mf++) {
                const uint32_t row = (uint32_t)(wm * 64 + mf * 16 + lrow);
                ldsm_x4(afr[mf], abase + SMEM_SWIZZLE_128B(row * 128 + colb));
            }
            uint32_t bfr[4][4];
            #pragma unroll
            for (int nq = 0; nq < 4; nq++) {
                const uint32_t row = (uint32_t)(wn * 64 + nq * 16 + lrow);
                ldsm_x4(bfr[nq], bbase + SMEM_SWIZZLE_128B(row * 128 + colb));
            }
            #pragma unroll
            for (int mf = 0; mf < 4; mf++) {
                #pragma unroll
                for (int nq = 0; nq < 4; nq++) {
                    mma16816(acc[mf][2 * nq + 0], afr[mf], bfr[nq][0], bfr[nq][2]);
                    mma16816(acc[mf][2 * nq + 1], afr[mf], bfr[nq][1], bfr[nq][3]);
                }
            }
        }
    }

    // epilogue: acc -> g_qkv16 fp16
    const int qrow = lane >> 2;          // 0..7
    const int qcol = (lane & 3) * 2;     // 0,2,4,6
    #pragma unroll
    for (int mf = 0; mf < 4; mf++) {
        const size_t r0 = m0 + wm * 64 + mf * 16 + qrow;
        #pragma unroll
        for (int nf = 0; nf < 8; nf++) {
            const size_t cidx = n0 + wn * 64 + nf * 8 + qcol;
            *(__half2*)(g_qkv16 + r0 * QKVC + cidx) =
                __floats2half2_rn(acc[mf][nf][0], acc[mf][nf][1]);
            *(__half2*)(g_qkv16 + (r0 + 8) * QKVC + cidx) =
                __floats2half2_rn(acc[mf][nf][2], acc[mf][nf][3]);
        }
    }
}

// ===========================================================================
// Fused attention: blocks [0,512) = spatial (mma.sync FA), [512,1024) = temporal.
// ===========================================================================
__global__ void __launch_bounds__(256, 1)
fused_attn(float* __restrict__ out)
{
    const int tid = threadIdx.x;

    if (blockIdx.x < 512) {
        // ----------------- spatial attention (mma.sync) -----------------
        extern __shared__ __align__(128) __half spm[];
        const uint32_t qs = smem_u32(spm);
        const uint32_t ks = qs + 32768;
        const uint32_t vs = qs + 65536;

        const int g = blockIdx.x;         // 0..511
        const int t = g & 15;
        const int h = (g >> 4) & 3;
        const int b = g >> 6;
        const int warp = tid >> 5, lane = tid & 31;

        const __half* src = g_qkv16 + ((size_t)b * NTOK + (size_t)t * S_ + tid) * QKVC + h * DH;
        #pragma unroll
        for (int i = 0; i < 8; i++) {
            const uint32_t off = SMEM_SWIZZLE_128B((uint32_t)(tid * 128 + i * 16));
            asm volatile("cp.async.cg.shared.global [%0], [%1], 16;"
                         :: "r"(qs + off), "l"(src + i * 8) : "memory");
            asm volatile("cp.async.cg.shared.global [%0], [%1], 16;"
                         :: "r"(ks + off), "l"(src + 512 + i * 8) : "memory");
            asm volatile("cp.async.cg.shared.global [%0], [%1], 16;"
                         :: "r"(vs + off), "l"(src + 1024 + i * 8) : "memory");
        }
        asm volatile("cp.async.commit_group;" ::: "memory");
        asm volatile("cp.async.wait_group 0;" ::: "memory");
        __syncthreads();

        const int lrow  = lane & 15;
        const int lhalf = (lane >> 4) * 16;
        const int m0 = warp * 32;

        uint32_t aq[2][4][4];
        #pragma unroll
        for (int st = 0; st < 2; st++)
            #pragma unroll
            for (int k16 = 0; k16 < 4; k16++) {
                const uint32_t row = (uint32_t)(m0 + st * 16 + lrow);
                ldsm_x4(aq[st][k16], qs + SMEM_SWIZZLE_128B(row * 128 + k16 * 32 + lhalf));
            }

        float o[2][8][4];
        #pragma unroll
        for (int st = 0; st < 2; st++)
            #pragma unroll
            for (int nt = 0; nt < 8; nt++)
                #pragma unroll
                for (int i = 0; i < 4; i++) o[st][nt][i] = 0.f;
        float l0[2] = {0.f, 0.f}, l1[2] = {0.f, 0.f};

        #pragma unroll 1
        for (int c = 0; c < 4; c++) {
            const int k0 = c * 64;

            float s[2][8][4];
            #pragma unroll
            for (int st = 0; st < 2; st++)
                #pragma unroll
                for (int nt = 0; nt < 8; nt++)
                    #pragma unroll
                    for (int i = 0; i < 4; i++) s[st][nt][i] = 0.f;

            #pragma unroll
            for (int k16 = 0; k16 < 4; k16++) {
                uint32_t kf[4][4];
                #pragma unroll
                for (int kg = 0; kg < 4; kg++) {
                    const uint32_t row = (uint32_t)(k0 + kg * 16 + lrow);
                    ldsm_x4(kf[kg], ks + SMEM_SWIZZLE_128B(row * 128 + k16 * 32 + lhalf));
                }
                #pragma unroll
                for (int st = 0; st < 2; st++)
                    #pragma unroll
                    for (int kg = 0; kg < 4; kg++) {
                        mma16816(s[st][2 * kg + 0], aq[st][k16], kf[kg][0], kf[kg][2]);
                        mma16816(s[st][2 * kg + 1], aq[st][k16], kf[kg][1], kf[kg][3]);
                    }
            }

            uint32_t pa[2][4][4];
            #pragma unroll
            for (int st = 0; st < 2; st++)
                #pragma unroll
                for (int nt = 0; nt < 8; nt++) {
                    const float p0 = __expf(s[st][nt][0] * 0.125f);
                    const float p1 = __expf(s[st][nt][1] * 0.125f);
                    const float p2 = __expf(s[st][nt][2] * 0.125f);
                    const float p3 = __expf(s[st][nt][3] * 0.125f);
                    l0[st] += p0 + p1;
                    l1[st] += p2 + p3;
                    const int kk = nt >> 1;
                    if (nt & 1) {
                        pa[st][kk][2] = pack_h2(p0, p1);
                        pa[st][kk][3] = pack_h2(p2, p3);
                    } else {
                        pa[st][kk][0] = pack_h2(p0, p1);
                        pa[st][kk][1] = pack_h2(p2, p3);
                    }
                }

            #pragma unroll
            for (int k16 = 0; k16 < 4; k16++) {
                uint32_t vf[8][2];
                #pragma unroll
                for (int j = 0; j < 4; j++) {
                    uint32_t r[4];
                    const uint32_t row = (uint32_t)(k0 + k16 * 16 + lrow);
                    ldsm_x4_t(r, vs + SMEM_SWIZZLE_128B(row * 128 + j * 32 + lhalf));
                    vf[2 * j + 0][0] = r[0]; vf[2 * j + 0][1] = r[1];
                    vf[2 * j + 1][0] = r[2]; vf[2 * j + 1][1] = r[3];
                }
                #pragma unroll
                for (int st = 0; st < 2; st++)
                    #pragma unroll
                    for (int nt = 0; nt < 8; nt++)
                        mma16816(o[st][nt], pa[st][k16], vf[nt][0], vf[nt][1]);
            }
        }

        #pragma unroll
        for (int st = 0; st < 2; st++) {
            l0[st] += __shfl_xor_sync(0xffffffffu, l0[st], 1);
            l0[st] += __shfl_xor_sync(0xffffffffu, l0[st], 2);
            l1[st] += __shfl_xor_sync(0xffffffffu, l1[st], 1);
            l1[st] += __shfl_xor_sync(0xffffffffu, l1[st], 2);
        }

        const size_t obase = (((size_t)b * H2_ + h) * NTOK + (size_t)t * S_) * DH;
        #pragma unroll
        for (int st = 0; st < 2; st++) {
            const float inv0 = 1.f / l0[st];
            const float inv1 = 1.f / l1[st];
            const int rlo = m0 + st * 16 + (lane >> 2);
            #pragma unroll
            for (int nt = 0; nt < 8; nt++) {
                const int col = nt * 8 + (lane & 3) * 2;
                *(float2*)(out + obase + (size_t)rlo * DH + col) =
                    make_float2(o[st][nt][0] * inv0, o[st][nt][1] * inv0);
                *(float2*)(out + obase + (size_t)(rlo + 8) * DH + col) =
                    make_float2(o[st][nt][2] * inv1, o[st][nt][3] * inv1);
            }
        }
    } else {
        // ----------------- temporal attention (scalar) -----------------
        const int idx = (blockIdx.x - 512) * 256 + tid;     // 0..131071
        const int i  = idx & 15;
        const int s  = (idx >> 4) & 255;
        const int h  = (idx >> 12) & 3;
        const int b  = idx >> 14;

        const __half* base = g_qkv16 + ((size_t)b * NTOK + (size_t)s * NT_) * QKVC + (h + 4) * DH;
        const __half* qptr = base + (size_t)i * QKVC;

        float q[DH];
        #pragma unroll
        for (int seg = 0; seg < 8; seg++)
            h8_to_f8(*(const uint4*)(qptr + seg * 8), &q[seg * 8]);

        float p[NT_];
        float l = 0.f;
        const __half* kb = base + 512;
        #pragma unroll
        for (int j = 0; j < NT_; j++) {
            const __half* kr = kb + (size_t)j * QKVC;
            float s0 = 0.f, s1 = 0.f, s2 = 0.f, s3 = 0.f;
            #pragma unroll
            for (int seg = 0; seg < 8; seg++) {
                float kf[8];
                h8_to_f8(*(const uint4*)(kr + seg * 8), kf);
                s0 = fmaf(q[8 * seg + 0], kf[0], s0);
                s1 = fmaf(q[8 * seg + 1], kf[1], s1);
                s2 = fmaf(q[8 * seg + 2], kf[2], s2);
                s3 = fmaf(q[8 * seg + 3], kf[3], s3);
                s0 = fmaf(q[8 * seg + 4], kf[4], s0);
                s1 = fmaf(q[8 * seg + 5], kf[5], s1);
                s2 = fmaf(q[8 * seg + 6], kf[6], s2);
                s3 = fmaf(q[8 * seg + 7], kf[7], s3);
            }
            p[j] = __expf(((s0 + s1) + (s2 + s3)) * 0.125f);
            l += p[j];
        }

        float acc[DH];
        #pragma unroll
        for (int d = 0; d < DH; d++) acc[d] = 0.f;
        const __half* vb = base + 1024;
        #pragma unroll
        for (int j = 0; j < NT_; j++) {
            const __half* vr = vb + (size_t)j * QKVC;
            const float pj = p[j];
            #pragma unroll
            for (int seg = 0; seg < 8; seg++) {
                float vf[8];
                h8_to_f8(*(const uint4*)(vr + seg * 8), vf);
                #pragma unroll
                for (int m = 0; m < 8; m++)
                    acc[8 * seg + m] = fmaf(pj, vf[m], acc[8 * seg + m]);
            }
        }

        const float inv = 1.f / l;
        float* op = out + ((((size_t)8 + b) * H2_ + h) * NTOK + (size_t)s * NT_ + i) * DH;
        #pragma unroll
        for (int d4 = 0; d4 < 16; d4++) {
            float4 o4 = make_float4(acc[4 * d4 + 0] * inv, acc[4 * d4 + 1] * inv,
                                    acc[4 * d4 + 2] * inv, acc[4 * d4 + 3] * inv);
            *(float4*)(op + d4 * 4) = o4;
        }
    }
}

// ---------------------------------------------------------------------------
extern "C" void kernel_launch(void* const* d_in, const int* in_sizes, int n_in,
                              void* d_out, int out_size)
{
    const float* x = (const float*)d_in[0];   // [8,4096,512]
    const float* w = (const float*)d_in[1];   // [512,1536]
    float* out = (float*)d_out;               // [2,8,4,4096,64]

    // 0) fp32 -> fp16 (A and B fused)
    const int nb_blk = (QKVC * 512) / 256;    // 3072
    conv_ab<<<NA_BLK + nb_blk, 256>>>(x, w);

    // 1) mma.sync fp16 GEMM -> g_qkv16 (256x128 tiles)
    const int gemm_smem = STAGES * STAGE_BYTES;          // 147456
    cudaFuncSetAttribute(qkv_gemm_mma, cudaFuncAttributeMaxDynamicSharedMemorySize, gemm_smem);
    dim3 ggrid(QKVC / 128, M_TOT / 256);                 // (12, 128)
    qkv_gemm_mma<<<ggrid, 256, gemm_smem>>>();

    // 2) fused spatial (mma) + temporal attention
    const int sp_smem = 3 * S_ * DH * (int)sizeof(__half);   // 98304
    cudaFuncSetAttribute(fused_attn, cudaFuncAttributeMaxDynamicSharedMemorySize, sp_smem);
    fused_attn<<<1024, 256, sp_smem>>>(out);
}

// round 7
// speedup vs baseline: 1.1594x; 1.1594x over previous
#include <cuda_runtime.h>
#include <cuda_fp16.h>
#include <cstdint>

// ---------------------------------------------------------------------------
// Problem constants
//   x:      [8, 4096, 512]  fp32
//   w_qkv:  [512, 1536]     fp32
//   out:    [2, 8, 4, 4096, 64] fp32
// g_qkv16 scratch: [32768, 1536] fp16 (q: 0..511, k: 512..1023, v: 1024..1535)
// ---------------------------------------------------------------------------
#define B_      8
#define NTOK    4096
#define DIM     512
#define QKVC    1536
#define NT_     16
#define S_      256
#define H2_     4
#define DH      64
#define M_TOT   (B_ * NTOK)          // 32768

__device__ __half g_qkv16[(size_t)M_TOT * QKVC];    // 100 MB
__device__ __half g_A[(size_t)M_TOT * DIM];         // 32 MB  [M, 512] fp16
__device__ __half g_B[(size_t)QKVC * DIM];          // 1.5 MB [N, 512] fp16 (K-major)

// ===========================================================================
// helpers
// ===========================================================================
__device__ __forceinline__ uint32_t smem_u32(const void* p) {
    uint32_t a;
    asm("{ .reg .u64 t; cvta.to.shared.u64 t, %1; cvt.u32.u64 %0, t; }"
        : "=r"(a) : "l"(p));
    return a;
}

#define SMEM_SWIZZLE_128B(byte_offset) \
    ((byte_offset) ^ (((byte_offset) >> 3) & 0x70))

__device__ __forceinline__ void ldsm_x4(uint32_t* r, uint32_t addr) {
    asm volatile("ldmatrix.sync.aligned.m8n8.x4.shared.b16 {%0,%1,%2,%3}, [%4];"
        : "=r"(r[0]), "=r"(r[1]), "=r"(r[2]), "=r"(r[3]) : "r"(addr));
}

__device__ __forceinline__ void ldsm_x4_t(uint32_t* r, uint32_t addr) {
    asm volatile("ldmatrix.sync.aligned.m8n8.x4.trans.shared.b16 {%0,%1,%2,%3}, [%4];"
        : "=r"(r[0]), "=r"(r[1]), "=r"(r[2]), "=r"(r[3]) : "r"(addr));
}

__device__ __forceinline__ void mma16816(float* d, const uint32_t* a,
                                         uint32_t b0, uint32_t b1) {
    asm volatile(
        "mma.sync.aligned.m16n8k16.row.col.f32.f16.f16.f32 "
        "{%0,%1,%2,%3}, {%4,%5,%6,%7}, {%8,%9}, {%0,%1,%2,%3};"
        : "+f"(d[0]), "+f"(d[1]), "+f"(d[2]), "+f"(d[3])
        : "r"(a[0]), "r"(a[1]), "r"(a[2]), "r"(a[3]), "r"(b0), "r"(b1));
}

__device__ __forceinline__ uint32_t pack_h2(float a, float b) {
    __half2 h = __floats2half2_rn(a, b);
    return *(uint32_t*)&h;
}

// ===========================================================================
// Fused conversion: fp32 -> fp16 for A (x) and B (w, transposed)
// ===========================================================================
#define NA_BLK (M_TOT * 128 / 256)      // 16384

__global__ void __launch_bounds__(256)
conv_ab(const float* __restrict__ x, const float* __restrict__ w)
{
    const int bidx = blockIdx.x;
    if (bidx < NA_BLK) {
        size_t idx = (size_t)bidx * 256 + threadIdx.x;   // 0 .. 32768*128-1
        size_t m = idx >> 7;
        int k4 = (int)(idx & 127);
        float4 v = *(const float4*)(x + m * DIM + (size_t)k4 * 4);
        __align__(8) __half h[4];
        h[0] = __float2half_rn(v.x);
        h[1] = __float2half_rn(v.y);
        h[2] = __float2half_rn(v.z);
        h[3] = __float2half_rn(v.w);
        *(uint2*)&g_A[m * DIM + (size_t)k4 * 4] = *(uint2*)h;
    } else {
        int idx = (bidx - NA_BLK) * 256 + threadIdx.x;   // 0..786431
        int n = idx >> 9;
        int k = idx & 511;
        g_B[(size_t)n * DIM + k] = __float2half_rn(w[(size_t)k * QKVC + n]);
    }
}

// ===========================================================================
// mma.sync fp16 GEMM: g_qkv16[M,1536] = A[M,512] @ B[N,512]^T  (fp32 accum)
// 128x128 block tile, BK=64 (8 chunks), 3-stage cp.async pipeline, 8 warps.
// (known-good R5 configuration)
// ===========================================================================
#define STAGES 3
#define CHUNKS 8
#define KC 64
#define STAGE_BYTES 32768   // A tile 16KB + B tile 16KB

__global__ void __launch_bounds__(256, 1)
qkv_gemm_mma()
{
    extern __shared__ char dsm_raw[];
    const uint32_t tile_base = smem_u32(dsm_raw);

    const int tid  = threadIdx.x;
    const int wid  = tid >> 5;
    const int lane = tid & 31;
    const int wm = wid & 3;          // 0..3 -> 32-row strip
    const int wn = wid >> 2;         // 0..1 -> 64-col strip
    const int bx = blockIdx.x;       // N tile 0..11
    const int by = blockIdx.y;       // M tile 0..255

    const size_t m0 = (size_t)by * 128;
    const size_t n0 = (size_t)bx * 128;

    const int ldRow  = tid >> 1;            // 0..127
    const int ldCol0 = (tid & 1) * 64;      // byte col 0 or 64

    auto load_chunk = [&](int c, int s) {
        const int kk = c * KC;
        const uint32_t abase = tile_base + s * STAGE_BYTES;
        const uint32_t bbase = abase + 16384;
        const __half* srcA = g_A + (m0 + ldRow) * DIM + kk + ldCol0 / 2;
        const __half* srcB = g_B + (n0 + ldRow) * DIM + kk + ldCol0 / 2;
        #pragma unroll
        for (int i = 0; i < 4; i++) {
            const uint32_t off = SMEM_SWIZZLE_128B((uint32_t)(ldRow * 128 + ldCol0 + i * 16));
            asm volatile("cp.async.cg.shared.global [%0], [%1], 16;"
                         :: "r"(abase + off), "l"(srcA + i * 8) : "memory");
            asm volatile("cp.async.cg.shared.global [%0], [%1], 16;"
                         :: "r"(bbase + off), "l"(srcB + i * 8) : "memory");
        }
    };

    float acc[2][8][4];
    #pragma unroll
    for (int mf = 0; mf < 2; mf++)
        #pragma unroll
        for (int nf = 0; nf < 8; nf++)
            #pragma unroll
            for (int i = 0; i < 4; i++) acc[mf][nf][i] = 0.f;

    load_chunk(0, 0);
    asm volatile("cp.async.commit_group;" ::: "memory");
    load_chunk(1, 1);
    asm volatile("cp.async.commit_group;" ::: "memory");

    const int lrow  = lane & 15;
    const int lhalf = (lane >> 4) * 16;

    #pragma unroll 1
    for (int c = 0; c < CHUNKS; c++) {
        asm volatile("cp.async.wait_group 1;" ::: "memory");
        __syncthreads();

        if (c + 2 < CHUNKS) load_chunk(c + 2, (c + 2) % STAGES);
        asm volatile("cp.async.commit_group;" ::: "memory");

        const uint32_t abase = tile_base + (c % STAGES) * STAGE_BYTES;
        const uint32_t bbase = abase + 16384;

        #pragma unroll
        for (int k16 = 0; k16 < 4; k16++) {
            const uint32_t colb = (uint32_t)(k16 * 32 + lhalf);
            uint32_t afr[2][4];
            #pragma unroll
            for (int mf = 0; mf < 2; mf++) {
                const uint32_t row = (uint32_t)(wm * 32 + mf * 16 + lrow);
                ldsm_x4(afr[mf], abase + SMEM_SWIZZLE_128B(row * 128 + colb));
            }
            uint32_t bfr[4][4];
            #pragma unroll
            for (int nq = 0; nq < 4; nq++) {
                const uint32_t row = (uint32_t)(wn * 64 + nq * 16 + lrow);
                ldsm_x4(bfr[nq], bbase + SMEM_SWIZZLE_128B(row * 128 + colb));
            }
            #pragma unroll
            for (int mf = 0; mf < 2; mf++) {
                #pragma unroll
                for (int nq = 0; nq < 4; nq++) {
                    mma16816(acc[mf][2 * nq + 0], afr[mf], bfr[nq][0], bfr[nq][2]);
                    mma16816(acc[mf][2 * nq + 1], afr[mf], bfr[nq][1], bfr[nq][3]);
                }
            }
        }
    }

    const int qrow = lane >> 2;          // 0..7
    const int qcol = (lane & 3) * 2;     // 0,2,4,6
    #pragma unroll
    for (int mf = 0; mf < 2; mf++) {
        const size_t r0 = m0 + wm * 32 + mf * 16 + qrow;
        #pragma unroll
        for (int nf = 0; nf < 8; nf++) {
            const size_t cidx = n0 + wn * 64 + nf * 8 + qcol;
            *(__half2*)(g_qkv16 + r0 * QKVC + cidx) =
                __floats2half2_rn(acc[mf][nf][0], acc[mf][nf][1]);
            *(__half2*)(g_qkv16 + (r0 + 8) * QKVC + cidx) =
                __floats2half2_rn(acc[mf][nf][2], acc[mf][nf][3]);
        }
    }
}

// ===========================================================================
// Fused attention, all-mma. 1024 blocks, 96 KB smem each:
//   blocks [0,512):    spatial  — one CTA per (b,h,t), 256q x 256k, d=64
//   blocks [512,1024): temporal — one CTA per (b,h,sc): 16 groups of 16x16
// Both stage Q,K,V 256x64 fp16 tiles in smem (SW128).
// ===========================================================================
__global__ void __launch_bounds__(256, 1)
fused_attn(float* __restrict__ out)
{
    extern __shared__ __align__(128) __half spm[];
    const uint32_t qs = smem_u32(spm);
    const uint32_t ks = qs + 32768;
    const uint32_t vs = qs + 65536;

    const int tid = threadIdx.x;
    const int warp = tid >> 5, lane = tid & 31;
    const int lrow  = lane & 15;
    const int lhalf = (lane >> 4) * 16;
    const bool is_spatial = blockIdx.x < 512;

    // ---- cooperative Q/K/V tile load (identical pattern for both phases) ----
    {
        const int g = is_spatial ? blockIdx.x : (blockIdx.x - 512);
        const int c0 = g & 15;          // t (spatial) or sc (temporal)
        const int h  = (g >> 4) & 3;
        const int b  = g >> 6;
        const int hoff = is_spatial ? h * DH : (4 + h) * DH;
        const __half* src = g_qkv16 + ((size_t)b * NTOK + (size_t)c0 * S_ + tid) * QKVC + hoff;
        #pragma unroll
        for (int i = 0; i < 8; i++) {
            const uint32_t off = SMEM_SWIZZLE_128B((uint32_t)(tid * 128 + i * 16));
            asm volatile("cp.async.cg.shared.global [%0], [%1], 16;"
                         :: "r"(qs + off), "l"(src + i * 8) : "memory");
            asm volatile("cp.async.cg.shared.global [%0], [%1], 16;"
                         :: "r"(ks + off), "l"(src + 512 + i * 8) : "memory");
            asm volatile("cp.async.cg.shared.global [%0], [%1], 16;"
                         :: "r"(vs + off), "l"(src + 1024 + i * 8) : "memory");
        }
        asm volatile("cp.async.commit_group;" ::: "memory");
        asm volatile("cp.async.wait_group 0;" ::: "memory");
        __syncthreads();
    }

    if (is_spatial) {
        // ----------------- spatial: full 256x256 attention -----------------
        const int g = blockIdx.x;
        const int t = g & 15;
        const int h = (g >> 4) & 3;
        const int b = g >> 6;
        const int m0 = warp * 32;

        uint32_t aq[2][4][4];
        #pragma unroll
        for (int st = 0; st < 2; st++)
            #pragma unroll
            for (int k16 = 0; k16 < 4; k16++) {
                const uint32_t row = (uint32_t)(m0 + st * 16 + lrow);
                ldsm_x4(aq[st][k16], qs + SMEM_SWIZZLE_128B(row * 128 + k16 * 32 + lhalf));
            }

        float o[2][8][4];
        #pragma unroll
        for (int st = 0; st < 2; st++)
            #pragma unroll
            for (int nt = 0; nt < 8; nt++)
                #pragma unroll
                for (int i = 0; i < 4; i++) o[st][nt][i] = 0.f;
        float l0[2] = {0.f, 0.f}, l1[2] = {0.f, 0.f};

        #pragma unroll 1
        for (int c = 0; c < 4; c++) {
            const int k0 = c * 64;

            float s[2][8][4];
            #pragma unroll
            for (int st = 0; st < 2; st++)
                #pragma unroll
                for (int nt = 0; nt < 8; nt++)
                    #pragma unroll
                    for (int i = 0; i < 4; i++) s[st][nt][i] = 0.f;

            #pragma unroll
            for (int k16 = 0; k16 < 4; k16++) {
                uint32_t kf[4][4];
                #pragma unroll
                for (int kg = 0; kg < 4; kg++) {
                    const uint32_t row = (uint32_t)(k0 + kg * 16 + lrow);
                    ldsm_x4(kf[kg], ks + SMEM_SWIZZLE_128B(row * 128 + k16 * 32 + lhalf));
                }
                #pragma unroll
                for (int st = 0; st < 2; st++)
                    #pragma unroll
                    for (int kg = 0; kg < 4; kg++) {
                        mma16816(s[st][2 * kg + 0], aq[st][k16], kf[kg][0], kf[kg][2]);
                        mma16816(s[st][2 * kg + 1], aq[st][k16], kf[kg][1], kf[kg][3]);
                    }
            }

            uint32_t pa[2][4][4];
            #pragma unroll
            for (int st = 0; st < 2; st++)
                #pragma unroll
                for (int nt = 0; nt < 8; nt++) {
                    const float p0 = __expf(s[st][nt][0] * 0.125f);
                    const float p1 = __expf(s[st][nt][1] * 0.125f);
                    const float p2 = __expf(s[st][nt][2] * 0.125f);
                    const float p3 = __expf(s[st][nt][3] * 0.125f);
                    l0[st] += p0 + p1;
                    l1[st] += p2 + p3;
                    const int kk = nt >> 1;
                    if (nt & 1) {
                        pa[st][kk][2] = pack_h2(p0, p1);
                        pa[st][kk][3] = pack_h2(p2, p3);
                    } else {
                        pa[st][kk][0] = pack_h2(p0, p1);
                        pa[st][kk][1] = pack_h2(p2, p3);
                    }
                }

            #pragma unroll
            for (int k16 = 0; k16 < 4; k16++) {
                uint32_t vf[8][2];
                #pragma unroll
                for (int j = 0; j < 4; j++) {
                    uint32_t r[4];
                    const uint32_t row = (uint32_t)(k0 + k16 * 16 + lrow);
                    ldsm_x4_t(r, vs + SMEM_SWIZZLE_128B(row * 128 + j * 32 + lhalf));
                    vf[2 * j + 0][0] = r[0]; vf[2 * j + 0][1] = r[1];
                    vf[2 * j + 1][0] = r[2]; vf[2 * j + 1][1] = r[3];
                }
                #pragma unroll
                for (int st = 0; st < 2; st++)
                    #pragma unroll
                    for (int nt = 0; nt < 8; nt++)
                        mma16816(o[st][nt], pa[st][k16], vf[nt][0], vf[nt][1]);
            }
        }

        #pragma unroll
        for (int st = 0; st < 2; st++) {
            l0[st] += __shfl_xor_sync(0xffffffffu, l0[st], 1);
            l0[st] += __shfl_xor_sync(0xffffffffu, l0[st], 2);
            l1[st] += __shfl_xor_sync(0xffffffffu, l1[st], 1);
            l1[st] += __shfl_xor_sync(0xffffffffu, l1[st], 2);
        }

        const size_t obase = (((size_t)b * H2_ + h) * NTOK + (size_t)t * S_) * DH;
        #pragma unroll
        for (int st = 0; st < 2; st++) {
            const float inv0 = 1.f / l0[st];
            const float inv1 = 1.f / l1[st];
            const int rlo = m0 + st * 16 + (lane >> 2);
            #pragma unroll
            for (int nt = 0; nt < 8; nt++) {
                const int col = nt * 8 + (lane & 3) * 2;
                *(float2*)(out + obase + (size_t)rlo * DH + col) =
                    make_float2(o[st][nt][0] * inv0, o[st][nt][1] * inv0);
                *(float2*)(out + obase + (size_t)(rlo + 8) * DH + col) =
                    make_float2(o[st][nt][2] * inv1, o[st][nt][3] * inv1);
            }
        }
    } else {
        // ------------- temporal: 16 independent 16x16 attentions -------------
        const int g = blockIdx.x - 512;
        const int sc = g & 15;
        const int h  = (g >> 4) & 3;
        const int b  = g >> 6;
        const int m0 = warp * 32;
        const size_t obase = ((((size_t)8 + b) * H2_ + h) * NTOK + (size_t)sc * S_) * DH;

        #pragma unroll
        for (int st = 0; st < 2; st++) {
            const int gbase = m0 + st * 16;     // this group's 16 rows
            const uint32_t grow = (uint32_t)(gbase + lrow);

            // Q A-frags and K B-frags, S = Q@K^T (16x16)
            float s[2][4] = {{0.f, 0.f, 0.f, 0.f}, {0.f, 0.f, 0.f, 0.f}};
            uint32_t pa[4];
            #pragma unroll
            for (int k16 = 0; k16 < 4; k16++) {
                uint32_t aq[4], kf[4];
                const uint32_t colb = (uint32_t)(k16 * 32 + lhalf);
                ldsm_x4(aq, qs + SMEM_SWIZZLE_128B(grow * 128 + colb));
                ldsm_x4(kf, ks + SMEM_SWIZZLE_128B(grow * 128 + colb));
                mma16816(s[0], aq, kf[0], kf[2]);
                mma16816(s[1], aq, kf[1], kf[3]);
            }

            // exp + row sums + repack to A-frag (single k16 of 16 keys)
            float l0 = 0.f, l1 = 0.f;
            #pragma unroll
            for (int nt = 0; nt < 2; nt++) {
                const float p0 = __expf(s[nt][0] * 0.125f);
                const float p1 = __expf(s[nt][1] * 0.125f);
                const float p2 = __expf(s[nt][2] * 0.125f);
                const float p3 = __expf(s[nt][3] * 0.125f);
                l0 += p0 + p1;
                l1 += p2 + p3;
                pa[2 * nt + 0] = pack_h2(p0, p1);
                pa[2 * nt + 1] = pack_h2(p2, p3);
            }
            l0 += __shfl_xor_sync(0xffffffffu, l0, 1);
            l0 += __shfl_xor_sync(0xffffffffu, l0, 2);
            l1 += __shfl_xor_sync(0xffffffffu, l1, 1);
            l1 += __shfl_xor_sync(0xffffffffu, l1, 2);

            // O = P @ V  (16x64, k=16)
            float o[8][4];
            #pragma unroll
            for (int nt = 0; nt < 8; nt++)
                #pragma unroll
                for (int i = 0; i < 4; i++) o[nt][i] = 0.f;
            #pragma unroll
            for (int j = 0; j < 4; j++) {
                uint32_t r[4];
                ldsm_x4_t(r, vs + SMEM_SWIZZLE_128B(grow * 128 + j * 32 + lhalf));
                mma16816(o[2 * j + 0], pa, r[0], r[1]);
                mma16816(o[2 * j + 1], pa, r[2], r[3]);
            }

            const float inv0 = 1.f / l0;
            const float inv1 = 1.f / l1;
            const int rlo = gbase + (lane >> 2);
            #pragma unroll
            for (int nt = 0; nt < 8; nt++) {
                const int col = nt * 8 + (lane & 3) * 2;
                *(float2*)(out + obase + (size_t)rlo * DH + col) =
                    make_float2(o[nt][0] * inv0, o[nt][1] * inv0);
                *(float2*)(out + obase + (size_t)(rlo + 8) * DH + col) =
                    make_float2(o[nt][2] * inv1, o[nt][3] * inv1);
            }
        }
    }
}

// ---------------------------------------------------------------------------
extern "C" void kernel_launch(void* const* d_in, const int* in_sizes, int n_in,
                              void* d_out, int out_size)
{
    const float* x = (const float*)d_in[0];   // [8,4096,512]
    const float* w = (const float*)d_in[1];   // [512,1536]
    float* out = (float*)d_out;               // [2,8,4,4096,64]

    // 0) fp32 -> fp16 (A and B fused)
    const int nb_blk = (QKVC * 512) / 256;    // 3072
    conv_ab<<<NA_BLK + nb_blk, 256>>>(x, w);

    // 1) mma.sync fp16 GEMM -> g_qkv16 (128x128 tiles, R5 config)
    const int gemm_smem = STAGES * STAGE_BYTES;          // 98304
    cudaFuncSetAttribute(qkv_gemm_mma, cudaFuncAttributeMaxDynamicSharedMemorySize, gemm_smem);
    dim3 ggrid(QKVC / 128, M_TOT / 128);                 // (12, 256)
    qkv_gemm_mma<<<ggrid, 256, gemm_smem>>>();

    // 2) fused all-mma attention (spatial + temporal), 96 KB smem
    const int sp_smem = 3 * S_ * DH * (int)sizeof(__half);   // 98304
    cudaFuncSetAttribute(fused_attn, cudaFuncAttributeMaxDynamicSharedMemorySize, sp_smem);
    fused_attn<<<1024, 256, sp_smem>>>(out);
}

// round 8
// speedup vs baseline: 1.1879x; 1.0245x over previous
#include <cuda_runtime.h>
#include <cuda_fp16.h>
#include <cstdint>

// ---------------------------------------------------------------------------
// Problem constants
//   x:      [8, 4096, 512]  fp32
//   w_qkv:  [512, 1536]     fp32
//   out:    [2, 8, 4, 4096, 64] fp32
// g_qkv16 scratch: [32768, 1536] fp16 (q: 0..511, k: 512..1023, v: 1024..1535)
// ---------------------------------------------------------------------------
#define B_      8
#define NTOK    4096
#define DIM     512
#define QKVC    1536
#define NT_     16
#define S_      256
#define H2_     4
#define DH      64
#define M_TOT   (B_ * NTOK)          // 32768

__device__ __half g_qkv16[(size_t)M_TOT * QKVC];    // 100 MB
__device__ __half g_A[(size_t)M_TOT * DIM];         // 32 MB  [M, 512] fp16
__device__ __half g_B[(size_t)QKVC * DIM];          // 1.5 MB [N, 512] fp16 (K-major)

// ===========================================================================
// helpers
// ===========================================================================
__device__ __forceinline__ uint32_t smem_u32(const void* p) {
    uint32_t a;
    asm("{ .reg .u64 t; cvta.to.shared.u64 t, %1; cvt.u32.u64 %0, t; }"
        : "=r"(a) : "l"(p));
    return a;
}

#define SMEM_SWIZZLE_128B(byte_offset) \
    ((byte_offset) ^ (((byte_offset) >> 3) & 0x70))

__device__ __forceinline__ void ldsm_x4(uint32_t* r, uint32_t addr) {
    asm volatile("ldmatrix.sync.aligned.m8n8.x4.shared.b16 {%0,%1,%2,%3}, [%4];"
        : "=r"(r[0]), "=r"(r[1]), "=r"(r[2]), "=r"(r[3]) : "r"(addr));
}

__device__ __forceinline__ void ldsm_x4_t(uint32_t* r, uint32_t addr) {
    asm volatile("ldmatrix.sync.aligned.m8n8.x4.trans.shared.b16 {%0,%1,%2,%3}, [%4];"
        : "=r"(r[0]), "=r"(r[1]), "=r"(r[2]), "=r"(r[3]) : "r"(addr));
}

__device__ __forceinline__ void mma16816(float* d, const uint32_t* a,
                                         uint32_t b0, uint32_t b1) {
    asm volatile(
        "mma.sync.aligned.m16n8k16.row.col.f32.f16.f16.f32 "
        "{%0,%1,%2,%3}, {%4,%5,%6,%7}, {%8,%9}, {%0,%1,%2,%3};"
        : "+f"(d[0]), "+f"(d[1]), "+f"(d[2]), "+f"(d[3])
        : "r"(a[0]), "r"(a[1]), "r"(a[2]), "r"(a[3]), "r"(b0), "r"(b1));
}

__device__ __forceinline__ uint32_t pack_h2(float a, float b) {
    __half2 h = __floats2half2_rn(a, b);
    return *(uint32_t*)&h;
}

// ===========================================================================
// Fused conversion: fp32 -> fp16
//   blocks [0, 8192):     A  (x [M,512] -> g_A, 8 elems/thread)
//   blocks [8192, 8384):  B  (w [512,1536] -> g_B [1536,512], smem transpose)
// ===========================================================================
#define NA_BLK2 8192
#define NB_TIL  192     // 8 k-tiles x 24 n-tiles of 64x64

__global__ void __launch_bounds__(256)
conv_ab(const float* __restrict__ x, const float* __restrict__ w)
{
    __shared__ __half st[64][72];    // [n][k], pad to 72 (144B rows, 16B-aligned)
    const int tid = threadIdx.x;
    const int bidx = blockIdx.x;

    if (bidx < NA_BLK2) {
        size_t idx = (size_t)bidx * 256 + tid;      // 0 .. 2097151
        size_t m = idx >> 6;
        int seg = (int)(idx & 63) * 8;
        const float* src = x + m * DIM + seg;
        float4 v0 = *(const float4*)(src);
        float4 v1 = *(const float4*)(src + 4);
        __align__(16) __half h[8];
        h[0] = __float2half_rn(v0.x); h[1] = __float2half_rn(v0.y);
        h[2] = __float2half_rn(v0.z); h[3] = __float2half_rn(v0.w);
        h[4] = __float2half_rn(v1.x); h[5] = __float2half_rn(v1.y);
        h[6] = __float2half_rn(v1.z); h[7] = __float2half_rn(v1.w);
        *(uint4*)&g_A[m * DIM + seg] = *(uint4*)h;
    } else {
        const int tb = bidx - NA_BLK2;
        const int kt = tb & 7;        // k tile (8 of 64)
        const int nt = tb >> 3;       // n tile (24 of 64)
        // read 64(k) x 64(n) fp32 coalesced, store transposed fp16 to smem
        #pragma unroll
        for (int it = 0; it < 4; it++) {
            const int row  = it * 16 + (tid >> 4);     // k within tile
            const int col4 = (tid & 15) * 4;           // n within tile
            float4 v = *(const float4*)(w + (size_t)(kt * 64 + row) * QKVC + nt * 64 + col4);
            st[col4 + 0][row] = __float2half_rn(v.x);
            st[col4 + 1][row] = __float2half_rn(v.y);
            st[col4 + 2][row] = __float2half_rn(v.z);
            st[col4 + 3][row] = __float2half_rn(v.w);
        }
        __syncthreads();
        // write g_B [n][k] in 16B chunks, coalesced
        #pragma unroll
        for (int it = 0; it < 2; it++) {
            const int n    = it * 32 + (tid >> 3);
            const int koff = (tid & 7) * 8;
            uint4 val = *(const uint4*)&st[n][koff];
            *(uint4*)&g_B[(size_t)(nt * 64 + n) * DIM + kt * 64 + koff] = val;
        }
    }
}

// ===========================================================================
// mma.sync fp16 GEMM: g_qkv16[M,1536] = A[M,512] @ B[N,512]^T  (fp32 accum)
// 128x128 block tile, BK=64 (8 chunks), 3-stage cp.async pipeline, 8 warps.
// (known-good R5 configuration — unchanged)
// ===========================================================================
#define STAGES 3
#define CHUNKS 8
#define KC 64
#define STAGE_BYTES 32768   // A tile 16KB + B tile 16KB

__global__ void __launch_bounds__(256, 1)
qkv_gemm_mma()
{
    extern __shared__ char dsm_raw[];
    const uint32_t tile_base = smem_u32(dsm_raw);

    const int tid  = threadIdx.x;
    const int wid  = tid >> 5;
    const int lane = tid & 31;
    const int wm = wid & 3;          // 0..3 -> 32-row strip
    const int wn = wid >> 2;         // 0..1 -> 64-col strip
    const int bx = blockIdx.x;       // N tile 0..11
    const int by = blockIdx.y;       // M tile 0..255

    const size_t m0 = (size_t)by * 128;
    const size_t n0 = (size_t)bx * 128;

    const int ldRow  = tid >> 1;            // 0..127
    const int ldCol0 = (tid & 1) * 64;      // byte col 0 or 64

    auto load_chunk = [&](int c, int s) {
        const int kk = c * KC;
        const uint32_t abase = tile_base + s * STAGE_BYTES;
        const uint32_t bbase = abase + 16384;
        const __half* srcA = g_A + (m0 + ldRow) * DIM + kk + ldCol0 / 2;
        const __half* srcB = g_B + (n0 + ldRow) * DIM + kk + ldCol0 / 2;
        #pragma unroll
        for (int i = 0; i < 4; i++) {
            const uint32_t off = SMEM_SWIZZLE_128B((uint32_t)(ldRow * 128 + ldCol0 + i * 16));
            asm volatile("cp.async.cg.shared.global [%0], [%1], 16;"
                         :: "r"(abase + off), "l"(srcA + i * 8) : "memory");
            asm volatile("cp.async.cg.shared.global [%0], [%1], 16;"
                         :: "r"(bbase + off), "l"(srcB + i * 8) : "memory");
        }
    };

    float acc[2][8][4];
    #pragma unroll
    for (int mf = 0; mf < 2; mf++)
        #pragma unroll
        for (int nf = 0; nf < 8; nf++)
            #pragma unroll
            for (int i = 0; i < 4; i++) acc[mf][nf][i] = 0.f;

    load_chunk(0, 0);
    asm volatile("cp.async.commit_group;" ::: "memory");
    load_chunk(1, 1);
    asm volatile("cp.async.commit_group;" ::: "memory");

    const int lrow  = lane & 15;
    const int lhalf = (lane >> 4) * 16;

    #pragma unroll 1
    for (int c = 0; c < CHUNKS; c++) {
        asm volatile("cp.async.wait_group 1;" ::: "memory");
        __syncthreads();

        if (c + 2 < CHUNKS) load_chunk(c + 2, (c + 2) % STAGES);
        asm volatile("cp.async.commit_group;" ::: "memory");

        const uint32_t abase = tile_base + (c % STAGES) * STAGE_BYTES;
        const uint32_t bbase = abase + 16384;

        #pragma unroll
        for (int k16 = 0; k16 < 4; k16++) {
            const uint32_t colb = (uint32_t)(k16 * 32 + lhalf);
            uint32_t afr[2][4];
            #pragma unroll
            for (int mf = 0; mf < 2; mf++) {
                const uint32_t row = (uint32_t)(wm * 32 + mf * 16 + lrow);
                ldsm_x4(afr[mf], abase + SMEM_SWIZZLE_128B(row * 128 + colb));
            }
            uint32_t bfr[4][4];
            #pragma unroll
            for (int nq = 0; nq < 4; nq++) {
                const uint32_t row = (uint32_t)(wn * 64 + nq * 16 + lrow);
                ldsm_x4(bfr[nq], bbase + SMEM_SWIZZLE_128B(row * 128 + colb));
            }
            #pragma unroll
            for (int mf = 0; mf < 2; mf++) {
                #pragma unroll
                for (int nq = 0; nq < 4; nq++) {
                    mma16816(acc[mf][2 * nq + 0], afr[mf], bfr[nq][0], bfr[nq][2]);
                    mma16816(acc[mf][2 * nq + 1], afr[mf], bfr[nq][1], bfr[nq][3]);
                }
            }
        }
    }

    const int qrow = lane >> 2;          // 0..7
    const int qcol = (lane & 3) * 2;     // 0,2,4,6
    #pragma unroll
    for (int mf = 0; mf < 2; mf++) {
        const size_t r0 = m0 + wm * 32 + mf * 16 + qrow;
        #pragma unroll
        for (int nf = 0; nf < 8; nf++) {
            const size_t cidx = n0 + wn * 64 + nf * 8 + qcol;
            *(__half2*)(g_qkv16 + r0 * QKVC + cidx) =
                __floats2half2_rn(acc[mf][nf][0], acc[mf][nf][1]);
            *(__half2*)(g_qkv16 + (r0 + 8) * QKVC + cidx) =
                __floats2half2_rn(acc[mf][nf][2], acc[mf][nf][3]);
        }
    }
}

// ===========================================================================
// Fused attention, all-mma, 2 CTAs/SM (regs <= 128 via sequential strips).
//   blocks [0,512):    spatial  — one CTA per (b,h,t), 256q x 256k, d=64
//   blocks [512,1024): temporal — one CTA per (b,h,sc): 16 groups of 16x16
// Both stage Q,K,V 256x64 fp16 tiles in smem (SW128, 96 KB).
// ===========================================================================
__global__ void __launch_bounds__(256, 2)
fused_attn(float* __restrict__ out)
{
    extern __shared__ __align__(128) __half spm[];
    const uint32_t qs = smem_u32(spm);
    const uint32_t ks = qs + 32768;
    const uint32_t vs = qs + 65536;

    const int tid = threadIdx.x;
    const int warp = tid >> 5, lane = tid & 31;
    const int lrow  = lane & 15;
    const int lhalf = (lane >> 4) * 16;
    const bool is_spatial = blockIdx.x < 512;

    // ---- cooperative Q/K/V tile load ----
    {
        const int g = is_spatial ? blockIdx.x : (blockIdx.x - 512);
        const int c0 = g & 15;
        const int h  = (g >> 4) & 3;
        const int b  = g >> 6;
        const int hoff = is_spatial ? h * DH : (4 + h) * DH;
        const __half* src = g_qkv16 + ((size_t)b * NTOK + (size_t)c0 * S_ + tid) * QKVC + hoff;
        #pragma unroll
        for (int i = 0; i < 8; i++) {
            const uint32_t off = SMEM_SWIZZLE_128B((uint32_t)(tid * 128 + i * 16));
            asm volatile("cp.async.cg.shared.global [%0], [%1], 16;"
                         :: "r"(qs + off), "l"(src + i * 8) : "memory");
            asm volatile("cp.async.cg.shared.global [%0], [%1], 16;"
                         :: "r"(ks + off), "l"(src + 512 + i * 8) : "memory");
            asm volatile("cp.async.cg.shared.global [%0], [%1], 16;"
                         :: "r"(vs + off), "l"(src + 1024 + i * 8) : "memory");
        }
        asm volatile("cp.async.commit_group;" ::: "memory");
        asm volatile("cp.async.wait_group 0;" ::: "memory");
        __syncthreads();
    }

    if (is_spatial) {
        // -------- spatial: 256x256, strips processed sequentially --------
        const int g = blockIdx.x;
        const int t = g & 15;
        const int h = (g >> 4) & 3;
        const int b = g >> 6;
        const int m0 = warp * 32;
        const size_t obase = (((size_t)b * H2_ + h) * NTOK + (size_t)t * S_) * DH;

        #pragma unroll 1
        for (int st = 0; st < 2; st++) {
            const int gb = m0 + st * 16;

            uint32_t aq[4][4];
            #pragma unroll
            for (int k16 = 0; k16 < 4; k16++)
                ldsm_x4(aq[k16], qs + SMEM_SWIZZLE_128B(
                    (uint32_t)(gb + lrow) * 128 + k16 * 32 + lhalf));

            float o[8][4];
            #pragma unroll
            for (int nt = 0; nt < 8; nt++)
                #pragma unroll
                for (int i = 0; i < 4; i++) o[nt][i] = 0.f;
            float l0 = 0.f, l1 = 0.f;

            #pragma unroll 1
            for (int c = 0; c < 4; c++) {
                const int k0 = c * 64;

                float s[8][4];
                #pragma unroll
                for (int nt = 0; nt < 8; nt++)
                    #pragma unroll
                    for (int i = 0; i < 4; i++) s[nt][i] = 0.f;

                #pragma unroll
                for (int k16 = 0; k16 < 4; k16++) {
                    const uint32_t colb = (uint32_t)(k16 * 32 + lhalf);
                    #pragma unroll
                    for (int kg = 0; kg < 4; kg++) {
                        uint32_t kf[4];
                        ldsm_x4(kf, ks + SMEM_SWIZZLE_128B(
                            (uint32_t)(k0 + kg * 16 + lrow) * 128 + colb));
                        mma16816(s[2 * kg + 0], aq[k16], kf[0], kf[2]);
                        mma16816(s[2 * kg + 1], aq[k16], kf[1], kf[3]);
                    }
                }

                uint32_t pa[4][4];
                #pragma unroll
                for (int nt = 0; nt < 8; nt++) {
                    const float p0 = __expf(s[nt][0] * 0.125f);
                    const float p1 = __expf(s[nt][1] * 0.125f);
                    const float p2 = __expf(s[nt][2] * 0.125f);
                    const float p3 = __expf(s[nt][3] * 0.125f);
                    l0 += p0 + p1;
                    l1 += p2 + p3;
                    const int kk = nt >> 1;
                    if (nt & 1) {
                        pa[kk][2] = pack_h2(p0, p1);
                        pa[kk][3] = pack_h2(p2, p3);
                    } else {
                        pa[kk][0] = pack_h2(p0, p1);
                        pa[kk][1] = pack_h2(p2, p3);
                    }
                }

                #pragma unroll
                for (int k16 = 0; k16 < 4; k16++) {
                    const uint32_t vrow = (uint32_t)(k0 + k16 * 16 + lrow);
                    #pragma unroll
                    for (int j = 0; j < 4; j++) {
                        uint32_t r[4];
                        ldsm_x4_t(r, vs + SMEM_SWIZZLE_128B(vrow * 128 + j * 32 + lhalf));
                        mma16816(o[2 * j + 0], pa[k16], r[0], r[1]);
                        mma16816(o[2 * j + 1], pa[k16], r[2], r[3]);
                    }
                }
            }

            l0 += __shfl_xor_sync(0xffffffffu, l0, 1);
            l0 += __shfl_xor_sync(0xffffffffu, l0, 2);
            l1 += __shfl_xor_sync(0xffffffffu, l1, 1);
            l1 += __shfl_xor_sync(0xffffffffu, l1, 2);

            const float inv0 = 1.f / l0;
            const float inv1 = 1.f / l1;
            const int rlo = gb + (lane >> 2);
            #pragma unroll
            for (int nt = 0; nt < 8; nt++) {
                const int col = nt * 8 + (lane & 3) * 2;
                *(float2*)(out + obase + (size_t)rlo * DH + col) =
                    make_float2(o[nt][0] * inv0, o[nt][1] * inv0);
                *(float2*)(out + obase + (size_t)(rlo + 8) * DH + col) =
                    make_float2(o[nt][2] * inv1, o[nt][3] * inv1);
            }
        }
    } else {
        // ------------- temporal: 16 independent 16x16 attentions -------------
        const int g = blockIdx.x - 512;
        const int sc = g & 15;
        const int h  = (g >> 4) & 3;
        const int b  = g >> 6;
        const int m0 = warp * 32;
        const size_t obase = ((((size_t)8 + b) * H2_ + h) * NTOK + (size_t)sc * S_) * DH;

        #pragma unroll 1
        for (int st = 0; st < 2; st++) {
            const int gbase = m0 + st * 16;
            const uint32_t grow = (uint32_t)(gbase + lrow);

            float s[2][4] = {{0.f, 0.f, 0.f, 0.f}, {0.f, 0.f, 0.f, 0.f}};
            uint32_t pa[4];
            #pragma unroll
            for (int k16 = 0; k16 < 4; k16++) {
                uint32_t aq[4], kf[4];
                const uint32_t colb = (uint32_t)(k16 * 32 + lhalf);
                ldsm_x4(aq, qs + SMEM_SWIZZLE_128B(grow * 128 + colb));
                ldsm_x4(kf, ks + SMEM_SWIZZLE_128B(grow * 128 + colb));
                mma16816(s[0], aq, kf[0], kf[2]);
                mma16816(s[1], aq, kf[1], kf[3]);
            }

            float l0 = 0.f, l1 = 0.f;
            #pragma unroll
            for (int nt = 0; nt < 2; nt++) {
                const float p0 = __expf(s[nt][0] * 0.125f);
                const float p1 = __expf(s[nt][1] * 0.125f);
                const float p2 = __expf(s[nt][2] * 0.125f);
                const float p3 = __expf(s[nt][3] * 0.125f);
                l0 += p0 + p1;
                l1 += p2 + p3;
                pa[2 * nt + 0] = pack_h2(p0, p1);
                pa[2 * nt + 1] = pack_h2(p2, p3);
            }
            l0 += __shfl_xor_sync(0xffffffffu, l0, 1);
            l0 += __shfl_xor_sync(0xffffffffu, l0, 2);
            l1 += __shfl_xor_sync(0xffffffffu, l1, 1);
            l1 += __shfl_xor_sync(0xffffffffu, l1, 2);

            float o[8][4];
            #pragma unroll
            for (int nt = 0; nt < 8; nt++)
                #pragma unroll
                for (int i = 0; i < 4; i++) o[nt][i] = 0.f;
            #pragma unroll
            for (int j = 0; j < 4; j++) {
                uint32_t r[4];
                ldsm_x4_t(r, vs + SMEM_SWIZZLE_128B(grow * 128 + j * 32 + lhalf));
                mma16816(o[2 * j + 0], pa, r[0], r[1]);
                mma16816(o[2 * j + 1], pa, r[2], r[3]);
            }

            const float inv0 = 1.f / l0;
            const float inv1 = 1.f / l1;
            const int rlo = gbase + (lane >> 2);
            #pragma unroll
            for (int nt = 0; nt < 8; nt++) {
                const int col = nt * 8 + (lane & 3) * 2;
                *(float2*)(out + obase + (size_t)rlo * DH + col) =
                    make_float2(o[nt][0] * inv0, o[nt][1] * inv0);
                *(float2*)(out + obase + (size_t)(rlo + 8) * DH + col) =
                    make_float2(o[nt][2] * inv1, o[nt][3] * inv1);
            }
        }
    }
}

// ---------------------------------------------------------------------------
extern "C" void kernel_launch(void* const* d_in, const int* in_sizes, int n_in,
                              void* d_out, int out_size)
{
    const float* x = (const float*)d_in[0];   // [8,4096,512]
    const float* w = (const float*)d_in[1];   // [512,1536]
    float* out = (float*)d_out;               // [2,8,4,4096,64]

    // 0) fp32 -> fp16 (A 8-elem/thread + B smem-transpose)
    conv_ab<<<NA_BLK2 + NB_TIL, 256>>>(x, w);

    // 1) mma.sync fp16 GEMM -> g_qkv16 (128x128 tiles, R5 config)
    const int gemm_smem = STAGES * STAGE_BYTES;          // 98304
    cudaFuncSetAttribute(qkv_gemm_mma, cudaFuncAttributeMaxDynamicSharedMemorySize, gemm_smem);
    dim3 ggrid(QKVC / 128, M_TOT / 128);                 // (12, 256)
    qkv_gemm_mma<<<ggrid, 256, gemm_smem>>>();

    // 2) fused all-mma attention (spatial + temporal), 96 KB smem, 2 CTA/SM
    const int sp_smem = 3 * S_ * DH * (int)sizeof(__half);   // 98304
    cudaFuncSetAttribute(fused_attn, cudaFuncAttributeMaxDynamicSharedMemorySize, sp_smem);
    fused_attn<<<1024, 256, sp_smem>>>(out);
}

// round 9
// speedup vs baseline: 1.3325x; 1.1218x over previous
#include <cuda_runtime.h>
#include <cuda_fp16.h>
#include <cstdint>

// ---------------------------------------------------------------------------
// Problem constants
//   x:      [8, 4096, 512]  fp32
//   w_qkv:  [512, 1536]     fp32
//   out:    [2, 8, 4, 4096, 64] fp32
// g_qkv16 scratch: [32768, 1536] fp16 (q: 0..511, k: 512..1023, v: 1024..1535)
// ---------------------------------------------------------------------------
#define B_      8
#define NTOK    4096
#define DIM     512
#define QKVC    1536
#define NT_     16
#define S_      256
#define H2_     4
#define DH      64
#define M_TOT   (B_ * NTOK)          // 32768

__device__ __half g_qkv16[(size_t)M_TOT * QKVC];    // 100 MB
__device__ __half g_A[(size_t)M_TOT * DIM];         // 32 MB  [M, 512] fp16
__device__ __half g_B[(size_t)QKVC * DIM];          // 1.5 MB [N, 512] fp16 (K-major)
__device__ int    g_sync[256];                      // per-M-tile GEMM completion

// ===========================================================================
// helpers
// ===========================================================================
__device__ __forceinline__ uint32_t smem_u32(const void* p) {
    uint32_t a;
    asm("{ .reg .u64 t; cvta.to.shared.u64 t, %1; cvt.u32.u64 %0, t; }"
        : "=r"(a) : "l"(p));
    return a;
}

#define SMEM_SWIZZLE_128B(byte_offset) \
    ((byte_offset) ^ (((byte_offset) >> 3) & 0x70))

__device__ __forceinline__ void ldsm_x4(uint32_t* r, uint32_t addr) {
    asm volatile("ldmatrix.sync.aligned.m8n8.x4.shared.b16 {%0,%1,%2,%3}, [%4];"
        : "=r"(r[0]), "=r"(r[1]), "=r"(r[2]), "=r"(r[3]) : "r"(addr));
}

__device__ __forceinline__ void ldsm_x4_t(uint32_t* r, uint32_t addr) {
    asm volatile("ldmatrix.sync.aligned.m8n8.x4.trans.shared.b16 {%0,%1,%2,%3}, [%4];"
        : "=r"(r[0]), "=r"(r[1]), "=r"(r[2]), "=r"(r[3]) : "r"(addr));
}

__device__ __forceinline__ void mma16816(float* d, const uint32_t* a,
                                         uint32_t b0, uint32_t b1) {
    asm volatile(
        "mma.sync.aligned.m16n8k16.row.col.f32.f16.f16.f32 "
        "{%0,%1,%2,%3}, {%4,%5,%6,%7}, {%8,%9}, {%0,%1,%2,%3};"
        : "+f"(d[0]), "+f"(d[1]), "+f"(d[2]), "+f"(d[3])
        : "r"(a[0]), "r"(a[1]), "r"(a[2]), "r"(a[3]), "r"(b0), "r"(b1));
}

__device__ __forceinline__ uint32_t pack_h2(float a, float b) {
    __half2 h = __floats2half2_rn(a, b);
    return *(uint32_t*)&h;
}

// ===========================================================================
// Fused conversion: fp32 -> fp16  (+ zero the sync flags from block 0)
//   blocks [0, 8192):     A  (x [M,512] -> g_A, 8 elems/thread)
//   blocks [8192, 8384):  B  (w [512,1536] -> g_B [1536,512], smem transpose)
// ===========================================================================
#define NA_BLK2 8192
#define NB_TIL  192     // 8 k-tiles x 24 n-tiles of 64x64

__global__ void __launch_bounds__(256)
conv_ab(const float* __restrict__ x, const float* __restrict__ w)
{
    __shared__ __half st[64][72];
    const int tid = threadIdx.x;
    const int bidx = blockIdx.x;

    if (bidx == 0) g_sync[tid] = 0;   // reset flags for this graph replay

    if (bidx < NA_BLK2) {
        size_t idx = (size_t)bidx * 256 + tid;      // 0 .. 2097151
        size_t m = idx >> 6;
        int seg = (int)(idx & 63) * 8;
        const float* src = x + m * DIM + seg;
        float4 v0 = *(const float4*)(src);
        float4 v1 = *(const float4*)(src + 4);
        __align__(16) __half h[8];
        h[0] = __float2half_rn(v0.x); h[1] = __float2half_rn(v0.y);
        h[2] = __float2half_rn(v0.z); h[3] = __float2half_rn(v0.w);
        h[4] = __float2half_rn(v1.x); h[5] = __float2half_rn(v1.y);
        h[6] = __float2half_rn(v1.z); h[7] = __float2half_rn(v1.w);
        *(uint4*)&g_A[m * DIM + seg] = *(uint4*)h;
    } else {
        const int tb = bidx - NA_BLK2;
        const int kt = tb & 7;        // k tile (8 of 64)
        const int nt = tb >> 3;       // n tile (24 of 64)
        #pragma unroll
        for (int it = 0; it < 4; it++) {
            const int row  = it * 16 + (tid >> 4);
            const int col4 = (tid & 15) * 4;
            float4 v = *(const float4*)(w + (size_t)(kt * 64 + row) * QKVC + nt * 64 + col4);
            st[col4 + 0][row] = __float2half_rn(v.x);
            st[col4 + 1][row] = __float2half_rn(v.y);
            st[col4 + 2][row] = __float2half_rn(v.z);
            st[col4 + 3][row] = __float2half_rn(v.w);
        }
        __syncthreads();
        #pragma unroll
        for (int it = 0; it < 2; it++) {
            const int n    = it * 32 + (tid >> 3);
            const int koff = (tid & 7) * 8;
            uint4 val = *(const uint4*)&st[n][koff];
            *(uint4*)&g_B[(size_t)(nt * 64 + n) * DIM + kt * 64 + koff] = val;
        }
    }
}

// ===========================================================================
// MEGA kernel: GEMM + attention in one grid with flag-based overlap.
//   blocks [0, 3072):    GEMM 128x128 tile; by = idx/12 (M-tile), bx = idx%12.
//                        After epilogue: signal g_sync[by].
//   blocks [3072, 4096): attention (spatial g<512, temporal g>=512); waits on
//                        g_sync for its two M-tiles, then runs as in R8.
// Dispatch is in blockIdx order, so every flag an attention CTA waits on is
// owned by earlier-indexed CTAs (resident or done) -> no deadlock.
// ===========================================================================
#define STAGES 3
#define CHUNKS 8
#define KC 64
#define STAGE_BYTES 32768   // A tile 16KB + B tile 16KB
#define GEMM_BLOCKS 3072

__global__ void __launch_bounds__(256, 2)
mega(float* __restrict__ out)
{
    extern __shared__ __align__(128) char dsm_raw[];
    const int tid  = threadIdx.x;
    const int bid  = blockIdx.x;

    if (bid < GEMM_BLOCKS) {
        // =============================== GEMM ===============================
        const uint32_t tile_base = smem_u32(dsm_raw);
        const int wid  = tid >> 5;
        const int lane = tid & 31;
        const int wm = wid & 3;
        const int wn = wid >> 2;
        const int by = bid / 12;
        const int bx = bid - by * 12;

        const size_t m0 = (size_t)by * 128;
        const size_t n0 = (size_t)bx * 128;

        const int ldRow  = tid >> 1;
        const int ldCol0 = (tid & 1) * 64;

        auto load_chunk = [&](int c, int s) {
            const int kk = c * KC;
            const uint32_t abase = tile_base + s * STAGE_BYTES;
            const uint32_t bbase = abase + 16384;
            const __half* srcA = g_A + (m0 + ldRow) * DIM + kk + ldCol0 / 2;
            const __half* srcB = g_B + (n0 + ldRow) * DIM + kk + ldCol0 / 2;
            #pragma unroll
            for (int i = 0; i < 4; i++) {
                const uint32_t off = SMEM_SWIZZLE_128B((uint32_t)(ldRow * 128 + ldCol0 + i * 16));
                asm volatile("cp.async.cg.shared.global [%0], [%1], 16;"
                             :: "r"(abase + off), "l"(srcA + i * 8) : "memory");
                asm volatile("cp.async.cg.shared.global [%0], [%1], 16;"
                             :: "r"(bbase + off), "l"(srcB + i * 8) : "memory");
            }
        };

        float acc[2][8][4];
        #pragma unroll
        for (int mf = 0; mf < 2; mf++)
            #pragma unroll
            for (int nf = 0; nf < 8; nf++)
                #pragma unroll
                for (int i = 0; i < 4; i++) acc[mf][nf][i] = 0.f;

        load_chunk(0, 0);
        asm volatile("cp.async.commit_group;" ::: "memory");
        load_chunk(1, 1);
        asm volatile("cp.async.commit_group;" ::: "memory");

        const int lrow  = lane & 15;
        const int lhalf = (lane >> 4) * 16;

        #pragma unroll 1
        for (int c = 0; c < CHUNKS; c++) {
            asm volatile("cp.async.wait_group 1;" ::: "memory");
            __syncthreads();

            if (c + 2 < CHUNKS) load_chunk(c + 2, (c + 2) % STAGES);
            asm volatile("cp.async.commit_group;" ::: "memory");

            const uint32_t abase = tile_base + (c % STAGES) * STAGE_BYTES;
            const uint32_t bbase = abase + 16384;

            #pragma unroll
            for (int k16 = 0; k16 < 4; k16++) {
                const uint32_t colb = (uint32_t)(k16 * 32 + lhalf);
                uint32_t afr[2][4];
                #pragma unroll
                for (int mf = 0; mf < 2; mf++) {
                    const uint32_t row = (uint32_t)(wm * 32 + mf * 16 + lrow);
                    ldsm_x4(afr[mf], abase + SMEM_SWIZZLE_128B(row * 128 + colb));
                }
                uint32_t bfr[4][4];
                #pragma unroll
                for (int nq = 0; nq < 4; nq++) {
                    const uint32_t row = (uint32_t)(wn * 64 + nq * 16 + lrow);
                    ldsm_x4(bfr[nq], bbase + SMEM_SWIZZLE_128B(row * 128 + colb));
                }
                #pragma unroll
                for (int mf = 0; mf < 2; mf++) {
                    #pragma unroll
                    for (int nq = 0; nq < 4; nq++) {
                        mma16816(acc[mf][2 * nq + 0], afr[mf], bfr[nq][0], bfr[nq][2]);
                        mma16816(acc[mf][2 * nq + 1], afr[mf], bfr[nq][1], bfr[nq][3]);
                    }
                }
            }
        }

        const int qrow = lane >> 2;
        const int qcol = (lane & 3) * 2;
        #pragma unroll
        for (int mf = 0; mf < 2; mf++) {
            const size_t r0 = m0 + wm * 32 + mf * 16 + qrow;
            #pragma unroll
            for (int nf = 0; nf < 8; nf++) {
                const size_t cidx = n0 + wn * 64 + nf * 8 + qcol;
                *(__half2*)(g_qkv16 + r0 * QKVC + cidx) =
                    __floats2half2_rn(acc[mf][nf][0], acc[mf][nf][1]);
                *(__half2*)(g_qkv16 + (r0 + 8) * QKVC + cidx) =
                    __floats2half2_rn(acc[mf][nf][2], acc[mf][nf][3]);
            }
        }

        // signal completion of this (by, bx) tile
        __threadfence();
        __syncthreads();
        if (tid == 0) atomicAdd(&g_sync[by], 1);
        return;
    }

    // =============================== attention ===============================
    const uint32_t qs = smem_u32(dsm_raw);
    const uint32_t ks = qs + 32768;
    const uint32_t vs = qs + 65536;

    const int warp = tid >> 5, lane = tid & 31;
    const int lrow  = lane & 15;
    const int lhalf = (lane >> 4) * 16;
    const int gp = bid - GEMM_BLOCKS;           // 0..1023
    const bool is_spatial = gp < 512;
    const int g  = is_spatial ? gp : gp - 512;
    const int c0 = g & 15;
    const int h  = (g >> 4) & 3;
    const int b  = g >> 6;

    // wait for the two producing M-tiles (12 N-tiles each)
    {
        const int by0 = b * 32 + c0 * 2;
        if (tid == 0) {
            volatile int* f = g_sync;
            while (f[by0] != 12)     __nanosleep(64);
            while (f[by0 + 1] != 12) __nanosleep(64);
            __threadfence();
        }
        __syncthreads();
    }

    // cooperative Q/K/V tile load
    {
        const int hoff = is_spatial ? h * DH : (4 + h) * DH;
        const __half* src = g_qkv16 + ((size_t)b * NTOK + (size_t)c0 * S_ + tid) * QKVC + hoff;
        #pragma unroll
        for (int i = 0; i < 8; i++) {
            const uint32_t off = SMEM_SWIZZLE_128B((uint32_t)(tid * 128 + i * 16));
            asm volatile("cp.async.cg.shared.global [%0], [%1], 16;"
                         :: "r"(qs + off), "l"(src + i * 8) : "memory");
            asm volatile("cp.async.cg.shared.global [%0], [%1], 16;"
                         :: "r"(ks + off), "l"(src + 512 + i * 8) : "memory");
            asm volatile("cp.async.cg.shared.global [%0], [%1], 16;"
                         :: "r"(vs + off), "l"(src + 1024 + i * 8) : "memory");
        }
        asm volatile("cp.async.commit_group;" ::: "memory");
        asm volatile("cp.async.wait_group 0;" ::: "memory");
        __syncthreads();
    }

    if (is_spatial) {
        // -------- spatial: 256x256, strips processed sequentially --------
        const int m0 = warp * 32;
        const size_t obase = (((size_t)b * H2_ + h) * NTOK + (size_t)c0 * S_) * DH;

        #pragma unroll 1
        for (int st = 0; st < 2; st++) {
            const int gb = m0 + st * 16;

            uint32_t aq[4][4];
            #pragma unroll
            for (int k16 = 0; k16 < 4; k16++)
                ldsm_x4(aq[k16], qs + SMEM_SWIZZLE_128B(
                    (uint32_t)(gb + lrow) * 128 + k16 * 32 + lhalf));

            float o[8][4];
            #pragma unroll
            for (int nt = 0; nt < 8; nt++)
                #pragma unroll
                for (int i = 0; i < 4; i++) o[nt][i] = 0.f;
            float l0 = 0.f, l1 = 0.f;

            #pragma unroll 1
            for (int c = 0; c < 4; c++) {
                const int k0 = c * 64;

                float s[8][4];
                #pragma unroll
                for (int nt = 0; nt < 8; nt++)
                    #pragma unroll
                    for (int i = 0; i < 4; i++) s[nt][i] = 0.f;

                #pragma unroll
                for (int k16 = 0; k16 < 4; k16++) {
                    const uint32_t colb = (uint32_t)(k16 * 32 + lhalf);
                    #pragma unroll
                    for (int kg = 0; kg < 4; kg++) {
                        uint32_t kf[4];
                        ldsm_x4(kf, ks + SMEM_SWIZZLE_128B(
                            (uint32_t)(k0 + kg * 16 + lrow) * 128 + colb));
                        mma16816(s[2 * kg + 0], aq[k16], kf[0], kf[2]);
                        mma16816(s[2 * kg + 1], aq[k16], kf[1], kf[3]);
                    }
                }

                uint32_t pa[4][4];
                #pragma unroll
                for (int nt = 0; nt < 8; nt++) {
                    const float p0 = __expf(s[nt][0] * 0.125f);
                    const float p1 = __expf(s[nt][1] * 0.125f);
                    const float p2 = __expf(s[nt][2] * 0.125f);
                    const float p3 = __expf(s[nt][3] * 0.125f);
                    l0 += p0 + p1;
                    l1 += p2 + p3;
                    const int kk = nt >> 1;
                    if (nt & 1) {
                        pa[kk][2] = pack_h2(p0, p1);
                        pa[kk][3] = pack_h2(p2, p3);
                    } else {
                        pa[kk][0] = pack_h2(p0, p1);
                        pa[kk][1] = pack_h2(p2, p3);
                    }
                }

                #pragma unroll
                for (int k16 = 0; k16 < 4; k16++) {
                    const uint32_t vrow = (uint32_t)(k0 + k16 * 16 + lrow);
                    #pragma unroll
                    for (int j = 0; j < 4; j++) {
                        uint32_t r[4];
                        ldsm_x4_t(r, vs + SMEM_SWIZZLE_128B(vrow * 128 + j * 32 + lhalf));
                        mma16816(o[2 * j + 0], pa[k16], r[0], r[1]);
                        mma16816(o[2 * j + 1], pa[k16], r[2], r[3]);
                    }
                }
            }

            l0 += __shfl_xor_sync(0xffffffffu, l0, 1);
            l0 += __shfl_xor_sync(0xffffffffu, l0, 2);
            l1 += __shfl_xor_sync(0xffffffffu, l1, 1);
            l1 += __shfl_xor_sync(0xffffffffu, l1, 2);

            const float inv0 = 1.f / l0;
            const float inv1 = 1.f / l1;
            const int rlo = gb + (lane >> 2);
            #pragma unroll
            for (int nt = 0; nt < 8; nt++) {
                const int col = nt * 8 + (lane & 3) * 2;
                *(float2*)(out + obase + (size_t)rlo * DH + col) =
                    make_float2(o[nt][0] * inv0, o[nt][1] * inv0);
                *(float2*)(out + obase + (size_t)(rlo + 8) * DH + col) =
                    make_float2(o[nt][2] * inv1, o[nt][3] * inv1);
            }
        }
    } else {
        // ------------- temporal: 16 independent 16x16 attentions -------------
        const int m0 = warp * 32;
        const size_t obase = ((((size_t)8 + b) * H2_ + h) * NTOK + (size_t)c0 * S_) * DH;

        #pragma unroll 1
        for (int st = 0; st < 2; st++) {
            const int gbase = m0 + st * 16;
            const uint32_t grow = (uint32_t)(gbase + lrow);

            float s[2][4] = {{0.f, 0.f, 0.f, 0.f}, {0.f, 0.f, 0.f, 0.f}};
            uint32_t pa[4];
            #pragma unroll
            for (int k16 = 0; k16 < 4; k16++) {
                uint32_t aq[4], kf[4];
                const uint32_t colb = (uint32_t)(k16 * 32 + lhalf);
                ldsm_x4(aq, qs + SMEM_SWIZZLE_128B(grow * 128 + colb));
                ldsm_x4(kf, ks + SMEM_SWIZZLE_128B(grow * 128 + colb));
                mma16816(s[0], aq, kf[0], kf[2]);
                mma16816(s[1], aq, kf[1], kf[3]);
            }

            float l0 = 0.f, l1 = 0.f;
            #pragma unroll
            for (int nt = 0; nt < 2; nt++) {
                const float p0 = __expf(s[nt][0] * 0.125f);
                const float p1 = __expf(s[nt][1] * 0.125f);
                const float p2 = __expf(s[nt][2] * 0.125f);
                const float p3 = __expf(s[nt][3] * 0.125f);
                l0 += p0 + p1;
                l1 += p2 + p3;
                pa[2 * nt + 0] = pack_h2(p0, p1);
                pa[2 * nt + 1] = pack_h2(p2, p3);
            }
            l0 += __shfl_xor_sync(0xffffffffu, l0, 1);
            l0 += __shfl_xor_sync(0xffffffffu, l0, 2);
            l1 += __shfl_xor_sync(0xffffffffu, l1, 1);
            l1 += __shfl_xor_sync(0xffffffffu, l1, 2);

            float o[8][4];
            #pragma unroll
            for (int nt = 0; nt < 8; nt++)
                #pragma unroll
                for (int i = 0; i < 4; i++) o[nt][i] = 0.f;
            #pragma unroll
            for (int j = 0; j < 4; j++) {
                uint32_t r[4];
                ldsm_x4_t(r, vs + SMEM_SWIZZLE_128B(grow * 128 + j * 32 + lhalf));
                mma16816(o[2 * j + 0], pa, r[0], r[1]);
                mma16816(o[2 * j + 1], pa, r[2], r[3]);
            }

            const float inv0 = 1.f / l0;
            const float inv1 = 1.f / l1;
            const int rlo = gbase + (lane >> 2);
            #pragma unroll
            for (int nt = 0; nt < 8; nt++) {
                const int col = nt * 8 + (lane & 3) * 2;
                *(float2*)(out + obase + (size_t)rlo * DH + col) =
                    make_float2(o[nt][0] * inv0, o[nt][1] * inv0);
                *(float2*)(out + obase + (size_t)(rlo + 8) * DH + col) =
                    make_float2(o[nt][2] * inv1, o[nt][3] * inv1);
            }
        }
    }
}

// ---------------------------------------------------------------------------
extern "C" void kernel_launch(void* const* d_in, const int* in_sizes, int n_in,
                              void* d_out, int out_size)
{
    const float* x = (const float*)d_in[0];   // [8,4096,512]
    const float* w = (const float*)d_in[1];   // [512,1536]
    float* out = (float*)d_out;               // [2,8,4,4096,64]

    // 0) fp32 -> fp16 + flag reset
    conv_ab<<<NA_BLK2 + NB_TIL, 256>>>(x, w);

    // 1) mega: GEMM (blocks 0..3071) + attention (blocks 3072..4095), overlapped
    const int mega_smem = STAGES * STAGE_BYTES;          // 98304
    cudaFuncSetAttribute(mega, cudaFuncAttributeMaxDynamicSharedMemorySize, mega_smem);
    mega<<<GEMM_BLOCKS + 1024, 256, mega_smem>>>(out);
}